// round 9
// baseline (speedup 1.0000x reference)
#include <cuda_runtime.h>
#include <cuda_bf16.h>
#include <stdint.h>

#define SEQ 80
#define EMB 100
#define VOCAB 10000
#define BMAX 16384
#define WSTRIDE 72   // padded bf16 row stride: conflict-free ldmatrix (verified R2/R8)

// Precomputed emb @ Wx0 + b0, columns permuted: unit j -> slot sidx_bf(j)
__device__ float g_embW0[VOCAB * 64];
// Transposed tokens [SEQ][B]
__device__ int g_tokT[SEQ * BMAX];

#define EMBW_BLOCKS 313

// slot of unit j: lane tq of half h reads 8 contiguous floats
__host__ __device__ __forceinline__ int sidx_bf(int j) {
    int h = j >> 5, ntl = (j >> 3) & 3, tq = (j >> 1) & 3, e = j & 1;
    return 32 * h + 8 * tq + 2 * ntl + e;
}

// ---------------------------------------------------------------------------
// Prep (fused): embW0 build (permuted cols) | token transpose
// ---------------------------------------------------------------------------
__global__ void __launch_bounds__(256) prep_kernel(const float* __restrict__ emb,
                                                   const float* __restrict__ Wx0,
                                                   const float* __restrict__ b0,
                                                   const int*   __restrict__ tokens,
                                                   int B) {
    int tid = threadIdx.x;
    if (blockIdx.x < EMBW_BLOCKS) {
        __shared__ float sW[EMB * 64];
        __shared__ float sE[32 * EMB];
        for (int i = tid; i < EMB * 64; i += 256) sW[i] = Wx0[i];
        int vbase = blockIdx.x * 32;
        for (int i = tid; i < 32 * EMB; i += 256) {
            int r = vbase + i / EMB;
            sE[i] = emb[(r < VOCAB ? r : 0) * EMB + i % EMB];
        }
        __syncthreads();

        int tcol = tid & 15;
        int trow = tid >> 4;
        float a0[4], a1[4];
        *reinterpret_cast<float4*>(a0) = *reinterpret_cast<const float4*>(b0 + tcol * 4);
        *reinterpret_cast<float4*>(a1) = *reinterpret_cast<float4*>(a0);
        const float* e0 = sE + trow * EMB;
        const float* e1 = sE + (trow + 16) * EMB;
        const float4* sW4 = reinterpret_cast<const float4*>(sW);
        #pragma unroll 10
        for (int k = 0; k < EMB; ++k) {
            float4 w = sW4[k * 16 + tcol];
            float ev0 = e0[k], ev1 = e1[k];
            a0[0] += ev0 * w.x; a0[1] += ev0 * w.y; a0[2] += ev0 * w.z; a0[3] += ev0 * w.w;
            a1[0] += ev1 * w.x; a1[1] += ev1 * w.y; a1[2] += ev1 * w.z; a1[3] += ev1 * w.w;
        }
        int v0 = vbase + trow, v1 = vbase + trow + 16;
        #pragma unroll
        for (int jj = 0; jj < 4; ++jj) {
            int s = sidx_bf(tcol * 4 + jj);
            if (v0 < VOCAB) g_embW0[v0 * 64 + s] = a0[jj];
            if (v1 < VOCAB) g_embW0[v1 * 64 + s] = a1[jj];
        }
        return;
    }
    int b = (blockIdx.x - EMBW_BLOCKS) * 256 + tid;
    if (b < B) {
        #pragma unroll
        for (int s = 0; s < SEQ; ++s)
            g_tokT[s * B + b] = tokens[b * SEQ + s];
    }
}

// ---------------------------------------------------------------------------
// PTX helpers
// ---------------------------------------------------------------------------
__device__ __forceinline__ void mma16816(float& d0, float& d1, float& d2, float& d3,
                                         uint32_t a0, uint32_t a1, uint32_t a2, uint32_t a3,
                                         uint32_t b0, uint32_t b1) {
    asm("mma.sync.aligned.m16n8k16.row.col.f32.bf16.bf16.f32 "
        "{%0,%1,%2,%3},{%4,%5,%6,%7},{%8,%9},{%0,%1,%2,%3};"
        : "+f"(d0), "+f"(d1), "+f"(d2), "+f"(d3)
        : "r"(a0), "r"(a1), "r"(a2), "r"(a3), "r"(b0), "r"(b1));
}

__device__ __forceinline__ void mma16816_c(float& d0, float& d1, float& d2, float& d3,
                                           uint32_t a0, uint32_t a1, uint32_t a2, uint32_t a3,
                                           uint32_t b0, uint32_t b1, float c0, float c1) {
    asm("mma.sync.aligned.m16n8k16.row.col.f32.bf16.bf16.f32 "
        "{%0,%1,%2,%3},{%4,%5,%6,%7},{%8,%9},{%10,%11,%10,%11};"
        : "=f"(d0), "=f"(d1), "=f"(d2), "=f"(d3)
        : "r"(a0), "r"(a1), "r"(a2), "r"(a3), "r"(b0), "r"(b1), "f"(c0), "f"(c1));
}

__device__ __forceinline__ void ldsm4(uint32_t& x, uint32_t& y, uint32_t& z, uint32_t& w,
                                      uint32_t saddr) {
    asm volatile("ldmatrix.sync.aligned.m8n8.x4.shared.b16 {%0,%1,%2,%3}, [%4];"
                 : "=r"(x), "=r"(y), "=r"(z), "=r"(w) : "r"(saddr));
}

__device__ __forceinline__ uint32_t packbf(float lo, float hi) {
    uint32_t r;
    asm("cvt.rn.bf16x2.f32 %0, %1, %2;" : "=r"(r) : "f"(hi), "f"(lo));
    return r;
}

__device__ __forceinline__ uint32_t tanh_bf16x2(uint32_t v) {
    uint32_t r;
    asm("tanh.approx.bf16x2 %0, %1;" : "=r"(r) : "r"(v));
    return r;
}

__device__ __forceinline__ float fast_tanh(float x) {
    float y;
    asm("tanh.approx.f32 %0, %1;" : "=f"(y) : "f"(x));
    return y;
}

// own-half acc[16] -> 8 bf16 A-frag words (tanh applied)
__device__ __forceinline__ void tanh_half_frags_bf(const float* acc, uint32_t* hw) {
    hw[0] = tanh_bf16x2(packbf(acc[0],  acc[1]));
    hw[1] = tanh_bf16x2(packbf(acc[8],  acc[9]));
    hw[2] = tanh_bf16x2(packbf(acc[2],  acc[3]));
    hw[3] = tanh_bf16x2(packbf(acc[10], acc[11]));
    hw[4] = tanh_bf16x2(packbf(acc[4],  acc[5]));
    hw[5] = tanh_bf16x2(packbf(acc[12], acc[13]));
    hw[6] = tanh_bf16x2(packbf(acc[6],  acc[7]));
    hw[7] = tanh_bf16x2(packbf(acc[14], acc[15]));
}

// ---------------------------------------------------------------------------
// Kernel 2: bf16 N-split recurrence, Wh0 B-fragments hoisted to registers.
// CTA = 64 threads = warp pair on 16 rows; per-step LDSM only for Wx1/Wh1.
// launch_bounds(64,7): 7 CTAs/SM -> 1036 slots >= 1024 CTAs (single wave).
// ---------------------------------------------------------------------------
__global__ void __launch_bounds__(64, 7) rnn_kernel(
    const float* __restrict__ Wh0,
    const float* __restrict__ Wx1,
    const float* __restrict__ Wh1,
    const float* __restrict__ b1,
    const float* __restrict__ Wout,
    const float* __restrict__ bout,
    float*       __restrict__ out,
    int B) {
    __shared__ __align__(16) uint16_t sWall[3 * 64 * WSTRIDE]; // Wh0^T,Wx1^T,Wh1^T
    __shared__ __align__(16) uint4 sEx[2][2][2][32];           // [layer][half][hi/lo][lane]
    __shared__ float sHd[2][16];

    {
        const float* Ws[3] = {Wh0, Wx1, Wh1};
        #pragma unroll
        for (int w = 0; w < 3; ++w) {
            for (int i = threadIdx.x; i < 64 * 64; i += 64) {
                int k = i >> 6, n = i & 63;
                __nv_bfloat16 v = __float2bfloat16(Ws[w][i]);
                sWall[w * 64 * WSTRIDE + n * WSTRIDE + k] =
                    *reinterpret_cast<uint16_t*>(&v);
            }
        }
    }
    __syncthreads();

    const int lane = threadIdx.x & 31;
    const int half = threadIdx.x >> 5;
    const int g  = lane >> 2;
    const int tq = lane & 3;
    const int base = blockIdx.x * 16;

    int rc[2];
    #pragma unroll
    for (int i = 0; i < 2; ++i) {
        int r = base + g + 8 * i;
        rc[i] = r < B ? r : (B - 1);
    }

    // ldmatrix base addressing (verified), shifted to own half's n rows
    const int laneoff = (lane & 7) * WSTRIDE + (lane >> 3) * 8;
    uint32_t swb = (uint32_t)__cvta_generic_to_shared(sWall);
    const uint32_t aW0 = swb + 2 * laneoff + 2 * (half * 4) * 8 * WSTRIDE;
    const uint32_t aW1 = aW0 + 2 * (64 * WSTRIDE);
    const uint32_t aW2 = aW1 + 2 * (64 * WSTRIDE);

    // ---- hoist Wh0 own-half B-fragments into registers (loop-invariant) ----
    uint32_t wf0[32];   // [(kp*4+ntl)*4 + {x,y,z,w}]
    #pragma unroll
    for (int kp = 0; kp < 2; ++kp) {
        #pragma unroll
        for (int ntl = 0; ntl < 4; ++ntl) {
            uint32_t off = 2 * (uint32_t)(ntl * 8 * WSTRIDE + kp * 32);
            int bi = (kp * 4 + ntl) * 4;
            ldsm4(wf0[bi + 0], wf0[bi + 1], wf0[bi + 2], wf0[bi + 3], aW0 + off);
        }
    }

    float b1f[8];
    #pragma unroll
    for (int nt = 0; nt < 4; ++nt) {
        b1f[nt * 2]     = b1[half * 32 + nt * 8 + tq * 2];
        b1f[nt * 2 + 1] = b1[half * 32 + nt * 8 + tq * 2 + 1];
    }

    float    accA[16], accB[16];   // [i(2)][ntl(4)][e(2)]
    uint32_t h0f[16], h1f[16];     // A-frags [k(4)][q(4)]
    #pragma unroll
    for (int i = 0; i < 16; ++i) { h0f[i] = 0u; h1f[i] = 0u; }

    // step-0 gather: own half = 8 contiguous floats per lane
    #pragma unroll
    for (int i = 0; i < 2; ++i) {
        int tok = g_tokT[rc[i]];
        const float* rowp = g_embW0 + tok * 64 + half * 32 + tq * 8;
        float4 v0 = *reinterpret_cast<const float4*>(rowp);
        float4 v1 = *reinterpret_cast<const float4*>(rowp + 4);
        accA[i*8+0]=v0.x; accA[i*8+1]=v0.y; accA[i*8+2]=v0.z; accA[i*8+3]=v0.w;
        accA[i*8+4]=v1.x; accA[i*8+5]=v1.y; accA[i*8+6]=v1.z; accA[i*8+7]=v1.w;
    }

    #pragma unroll 1
    for (int ts = 0; ts < SEQ; ++ts) {
        int tsn = (ts + 1 < SEQ) ? ts + 1 : SEQ - 1;
        int tkn[2];
        #pragma unroll
        for (int i = 0; i < 2; ++i) tkn[i] = g_tokT[tsn * B + rc[i]];

        // interleaved: accA += h0@Wh0 (regs) ; accB = b1 + h1@Wh1 (ldsm)
        #pragma unroll
        for (int kp = 0; kp < 2; ++kp) {
            #pragma unroll
            for (int ntl = 0; ntl < 4; ++ntl) {
                uint32_t off = 2 * (uint32_t)(ntl * 8 * WSTRIDE + kp * 32);
                int bi = (kp * 4 + ntl) * 4;
                uint32_t x2, y2, z2, w2;
                ldsm4(x2, y2, z2, w2, aW2 + off);
                int k0 = 2 * kp;
                mma16816(accA[ntl*2], accA[ntl*2+1], accA[8+ntl*2], accA[8+ntl*2+1],
                         h0f[k0*4+0], h0f[k0*4+1], h0f[k0*4+2], h0f[k0*4+3],
                         wf0[bi + 0], wf0[bi + 1]);
                if (kp == 0) {
                    mma16816_c(accB[ntl*2], accB[ntl*2+1], accB[8+ntl*2], accB[8+ntl*2+1],
                               h1f[0], h1f[1], h1f[2], h1f[3], x2, y2,
                               b1f[2*ntl], b1f[2*ntl+1]);
                } else {
                    mma16816(accB[ntl*2], accB[ntl*2+1], accB[8+ntl*2], accB[8+ntl*2+1],
                             h1f[k0*4+0], h1f[k0*4+1], h1f[k0*4+2], h1f[k0*4+3], x2, y2);
                }
                mma16816(accA[ntl*2], accA[ntl*2+1], accA[8+ntl*2], accA[8+ntl*2+1],
                         h0f[(k0+1)*4+0], h0f[(k0+1)*4+1], h0f[(k0+1)*4+2], h0f[(k0+1)*4+3],
                         wf0[bi + 2], wf0[bi + 3]);
                mma16816(accB[ntl*2], accB[ntl*2+1], accB[8+ntl*2], accB[8+ntl*2+1],
                         h1f[(k0+1)*4+0], h1f[(k0+1)*4+1], h1f[(k0+1)*4+2], h1f[(k0+1)*4+3],
                         z2, w2);
            }
        }

        // h0 own half = tanh(accA) -> 8 A-frag words
        uint32_t hw[8];
        tanh_half_frags_bf(accA, hw);

        // prefetch next-step gather into accA (now free)
        #pragma unroll
        for (int i = 0; i < 2; ++i) {
            const float* rowp = g_embW0 + tkn[i] * 64 + half * 32 + tq * 8;
            float4 v0 = *reinterpret_cast<const float4*>(rowp);
            float4 v1 = *reinterpret_cast<const float4*>(rowp + 4);
            accA[i*8+0]=v0.x; accA[i*8+1]=v0.y; accA[i*8+2]=v0.z; accA[i*8+3]=v0.w;
            accA[i*8+4]=v1.x; accA[i*8+5]=v1.y; accA[i*8+6]=v1.z; accA[i*8+7]=v1.w;
        }

        // exchange h0 halves
        sEx[0][half][0][lane] = make_uint4(hw[0], hw[1], hw[2], hw[3]);
        sEx[0][half][1][lane] = make_uint4(hw[4], hw[5], hw[6], hw[7]);
        __syncthreads();
        {
            uint4 p0 = sEx[0][half ^ 1][0][lane];
            uint4 p1 = sEx[0][half ^ 1][1][lane];
            int own = half * 8, oth = (half ^ 1) * 8;
            #pragma unroll
            for (int i = 0; i < 8; ++i) h0f[own + i] = hw[i];
            h0f[oth+0]=p0.x; h0f[oth+1]=p0.y; h0f[oth+2]=p0.z; h0f[oth+3]=p0.w;
            h0f[oth+4]=p1.x; h0f[oth+5]=p1.y; h0f[oth+6]=p1.z; h0f[oth+7]=p1.w;
        }

        // accB += h0new @ Wx1 (own n-tiles, full K)
        #pragma unroll
        for (int kp = 0; kp < 2; ++kp) {
            #pragma unroll
            for (int ntl = 0; ntl < 4; ++ntl) {
                uint32_t off = 2 * (uint32_t)(ntl * 8 * WSTRIDE + kp * 32);
                uint32_t x1, y1, z1, w1;
                ldsm4(x1, y1, z1, w1, aW1 + off);
                int k0 = 2 * kp;
                mma16816(accB[ntl*2], accB[ntl*2+1], accB[8+ntl*2], accB[8+ntl*2+1],
                         h0f[k0*4+0], h0f[k0*4+1], h0f[k0*4+2], h0f[k0*4+3], x1, y1);
                mma16816(accB[ntl*2], accB[ntl*2+1], accB[8+ntl*2], accB[8+ntl*2+1],
                         h0f[(k0+1)*4+0], h0f[(k0+1)*4+1], h0f[(k0+1)*4+2], h0f[(k0+1)*4+3],
                         z1, w1);
            }
        }

        // h1 own half = tanh(accB); exchange
        tanh_half_frags_bf(accB, hw);
        sEx[1][half][0][lane] = make_uint4(hw[0], hw[1], hw[2], hw[3]);
        sEx[1][half][1][lane] = make_uint4(hw[4], hw[5], hw[6], hw[7]);
        __syncthreads();
        {
            uint4 p0 = sEx[1][half ^ 1][0][lane];
            uint4 p1 = sEx[1][half ^ 1][1][lane];
            int own = half * 8, oth = (half ^ 1) * 8;
            #pragma unroll
            for (int i = 0; i < 8; ++i) h1f[own + i] = hw[i];
            h1f[oth+0]=p0.x; h1f[oth+1]=p0.y; h1f[oth+2]=p0.z; h1f[oth+3]=p0.w;
            h1f[oth+4]=p1.x; h1f[oth+5]=p1.y; h1f[oth+6]=p1.z; h1f[oth+7]=p1.w;
        }
    }

    // ---- head: sigmoid(tanh(accB) @ Wout + bout), halves combined via smem ----
    float wo[8];
    #pragma unroll
    for (int nt = 0; nt < 4; ++nt) {
        float2 v = *reinterpret_cast<const float2*>(Wout + half * 32 + nt * 8 + tq * 2);
        wo[nt * 2] = v.x; wo[nt * 2 + 1] = v.y;
    }
    float bo = bout[0];
    float sv[2];
    #pragma unroll
    for (int i = 0; i < 2; ++i) {
        float s = 0.f;
        #pragma unroll
        for (int nt = 0; nt < 4; ++nt) {
            s += fast_tanh(accB[i * 8 + nt * 2])     * wo[nt * 2];
            s += fast_tanh(accB[i * 8 + nt * 2 + 1]) * wo[nt * 2 + 1];
        }
        s += __shfl_xor_sync(0xffffffffu, s, 1);
        s += __shfl_xor_sync(0xffffffffu, s, 2);
        sv[i] = s;
        if (tq == 0) sHd[half][i * 8 + g] = s;
    }
    __syncthreads();
    if (half == 0 && tq == 0) {
        #pragma unroll
        for (int i = 0; i < 2; ++i) {
            int r = base + g + 8 * i;
            if (r < B) {
                float tot = sv[i] + sHd[1][i * 8 + g] + bo;
                out[r] = 1.0f / (1.0f + __expf(-tot));
            }
        }
    }
}

// ---------------------------------------------------------------------------
extern "C" void kernel_launch(void* const* d_in, const int* in_sizes, int n_in,
                              void* d_out, int out_size) {
    const int*   tokens = (const int*)  d_in[0];
    const float* emb    = (const float*)d_in[1];
    const float* Wx0    = (const float*)d_in[2];
    const float* Wh0    = (const float*)d_in[3];
    const float* b0     = (const float*)d_in[4];
    const float* Wx1    = (const float*)d_in[5];
    const float* Wh1    = (const float*)d_in[6];
    const float* b1     = (const float*)d_in[7];
    const float* Wout   = (const float*)d_in[8];
    const float* bout   = (const float*)d_in[9];
    float* out = (float*)d_out;

    int B = in_sizes[0] / SEQ;
    if (B > BMAX) B = BMAX;

    int prep_blocks = EMBW_BLOCKS + (B + 255) / 256;
    prep_kernel<<<prep_blocks, 256>>>(emb, Wx0, b0, tokens, B);

    int nblocks = (B + 15) / 16;
    rnn_kernel<<<nblocks, 64>>>(Wh0, Wx1, Wh1, b1, Wout, bout, out, B);
}

// round 10
// speedup vs baseline: 1.4976x; 1.4976x over previous
#include <cuda_runtime.h>
#include <cuda_bf16.h>
#include <stdint.h>

#define SEQ 80
#define EMB 100
#define VOCAB 10000
#define BMAX 16384
#define WSTRIDE 72   // padded bf16 row stride: conflict-free ldmatrix (verified R2/R8)

// Precomputed emb @ Wx0 + b0, columns permuted: col j -> slot sidx_full(j)
__device__ float g_embW0[VOCAB * 64];
// Transposed tokens [SEQ][B]
__device__ int g_tokT[SEQ * BMAX];
// Pre-swizzled bf16 weight image (exact smem layout): Wh0^T, Wx1^T, Wh1^T
__device__ uint16_t g_wsm[3 * 64 * WSTRIDE];

#define EMBW_BLOCKS 313

// storage slot of unit j: thread tq's 16 values land contiguous
//   j = 8nt + 2tq + e  ->  slot = 16tq + 2nt + e
__host__ __device__ __forceinline__ int sidx_full(int j) {
    int nt = j >> 3, tq = (j >> 1) & 3, e = j & 1;
    return 16 * tq + 2 * nt + e;
}

// ---------------------------------------------------------------------------
// Prep (fused): embW0 (permuted cols) | weight image | token transpose
// ---------------------------------------------------------------------------
__global__ void __launch_bounds__(256) prep_kernel(const float* __restrict__ emb,
                                                   const float* __restrict__ Wx0,
                                                   const float* __restrict__ b0,
                                                   const float* __restrict__ Wh0,
                                                   const float* __restrict__ Wx1,
                                                   const float* __restrict__ Wh1,
                                                   const int*   __restrict__ tokens,
                                                   int B) {
    int tid = threadIdx.x;
    if (blockIdx.x < EMBW_BLOCKS) {
        __shared__ float sW[EMB * 64];
        __shared__ float sE[32 * EMB];
        for (int i = tid; i < EMB * 64; i += 256) sW[i] = Wx0[i];
        int vbase = blockIdx.x * 32;
        for (int i = tid; i < 32 * EMB; i += 256) {
            int r = vbase + i / EMB;
            sE[i] = emb[(r < VOCAB ? r : 0) * EMB + i % EMB];
        }
        __syncthreads();

        int tcol = tid & 15;
        int trow = tid >> 4;
        float a0[4], a1[4];
        *reinterpret_cast<float4*>(a0) = *reinterpret_cast<const float4*>(b0 + tcol * 4);
        *reinterpret_cast<float4*>(a1) = *reinterpret_cast<float4*>(a0);
        const float* e0 = sE + trow * EMB;
        const float* e1 = sE + (trow + 16) * EMB;
        const float4* sW4 = reinterpret_cast<const float4*>(sW);
        #pragma unroll 10
        for (int k = 0; k < EMB; ++k) {
            float4 w = sW4[k * 16 + tcol];
            float ev0 = e0[k], ev1 = e1[k];
            a0[0] += ev0 * w.x; a0[1] += ev0 * w.y; a0[2] += ev0 * w.z; a0[3] += ev0 * w.w;
            a1[0] += ev1 * w.x; a1[1] += ev1 * w.y; a1[2] += ev1 * w.z; a1[3] += ev1 * w.w;
        }
        int v0 = vbase + trow, v1 = vbase + trow + 16;
        #pragma unroll
        for (int jj = 0; jj < 4; ++jj) {
            int s = sidx_full(tcol * 4 + jj);
            if (v0 < VOCAB) g_embW0[v0 * 64 + s] = a0[jj];
            if (v1 < VOCAB) g_embW0[v1 * 64 + s] = a1[jj];
        }
        return;
    }
    if (blockIdx.x == EMBW_BLOCKS) {
        // weight image: g_wsm[w*64*WSTRIDE + n*WSTRIDE + k] = bf16(W[k*64+n])
        const float* Ws[3] = {Wh0, Wx1, Wh1};
        for (int i = tid; i < 3 * 64 * 64; i += 256) {
            int w = i >> 12, r = i & 4095;
            int k = r >> 6, n = r & 63;
            __nv_bfloat16 v = __float2bfloat16(Ws[w][r]);
            g_wsm[w * 64 * WSTRIDE + n * WSTRIDE + k] = *reinterpret_cast<uint16_t*>(&v);
        }
        return;
    }
    int b = (blockIdx.x - EMBW_BLOCKS - 1) * 256 + tid;
    if (b < B) {
        #pragma unroll
        for (int s = 0; s < SEQ; ++s)
            g_tokT[s * B + b] = tokens[b * SEQ + s];
    }
}

// ---------------------------------------------------------------------------
// PTX helpers (all verified in earlier rounds)
// ---------------------------------------------------------------------------
__device__ __forceinline__ void mma16816(float& d0, float& d1, float& d2, float& d3,
                                         uint32_t a0, uint32_t a1, uint32_t a2, uint32_t a3,
                                         uint32_t b0, uint32_t b1) {
    asm("mma.sync.aligned.m16n8k16.row.col.f32.bf16.bf16.f32 "
        "{%0,%1,%2,%3},{%4,%5,%6,%7},{%8,%9},{%0,%1,%2,%3};"
        : "+f"(d0), "+f"(d1), "+f"(d2), "+f"(d3)
        : "r"(a0), "r"(a1), "r"(a2), "r"(a3), "r"(b0), "r"(b1));
}

__device__ __forceinline__ void mma16816_c(float& d0, float& d1, float& d2, float& d3,
                                           uint32_t a0, uint32_t a1, uint32_t a2, uint32_t a3,
                                           uint32_t b0, uint32_t b1, float c0, float c1) {
    asm("mma.sync.aligned.m16n8k16.row.col.f32.bf16.bf16.f32 "
        "{%0,%1,%2,%3},{%4,%5,%6,%7},{%8,%9},{%10,%11,%10,%11};"
        : "=f"(d0), "=f"(d1), "=f"(d2), "=f"(d3)
        : "r"(a0), "r"(a1), "r"(a2), "r"(a3), "r"(b0), "r"(b1), "f"(c0), "f"(c1));
}

__device__ __forceinline__ void ldsm4(uint32_t& x, uint32_t& y, uint32_t& z, uint32_t& w,
                                      uint32_t saddr) {
    asm volatile("ldmatrix.sync.aligned.m8n8.x4.shared.b16 {%0,%1,%2,%3}, [%4];"
                 : "=r"(x), "=r"(y), "=r"(z), "=r"(w) : "r"(saddr));
}

__device__ __forceinline__ uint32_t packbf(float lo, float hi) {
    uint32_t r;
    asm("cvt.rn.bf16x2.f32 %0, %1, %2;" : "=r"(r) : "f"(hi), "f"(lo));
    return r;
}

__device__ __forceinline__ uint32_t tanh_bf16x2(uint32_t v) {
    uint32_t r;
    asm("tanh.approx.bf16x2 %0, %1;" : "=r"(r) : "r"(v));
    return r;
}

__device__ __forceinline__ float fast_tanh(float x) {
    float y;
    asm("tanh.approx.f32 %0, %1;" : "=f"(y) : "f"(x));
    return y;
}

// acc[32] -> h[16] A-frag words (R2-verified mapping), tanh applied
__device__ __forceinline__ void tanh_frags(const float* acc, uint32_t* h) {
    #pragma unroll
    for (int k = 0; k < 4; ++k) {
        h[k*4+0] = tanh_bf16x2(packbf(acc[4*k],      acc[4*k+1]));
        h[k*4+1] = tanh_bf16x2(packbf(acc[16+4*k],   acc[16+4*k+1]));
        h[k*4+2] = tanh_bf16x2(packbf(acc[4*k+2],    acc[4*k+3]));
        h[k*4+3] = tanh_bf16x2(packbf(acc[16+4*k+2], acc[16+4*k+3]));
    }
}

// ---------------------------------------------------------------------------
// Kernel 2: bf16 recurrence. ONE warp per CTA (M=16 rows, full N=64),
// grid = B/16 = 1024 -> 7 CTAs/SM, perfectly balanced, single wave.
// No barriers, no exchanges. Wh0 B-frags hoisted to regs (64 words) —
// register budget is free because smem (27.6KB/CTA) caps residency at 7-8.
// ---------------------------------------------------------------------------
__global__ void __launch_bounds__(32, 7) rnn_kernel(
    const float* __restrict__ b1,
    const float* __restrict__ Wout,
    const float* __restrict__ bout,
    float*       __restrict__ out,
    int B) {
    __shared__ __align__(16) uint16_t sW[3 * 64 * WSTRIDE];

    // preamble: copy pre-swizzled weight image (1728 uint4, 54 per thread)
    {
        const uint4* src = reinterpret_cast<const uint4*>(g_wsm);
        uint4* dst = reinterpret_cast<uint4*>(sW);
        #pragma unroll 6
        for (int i = threadIdx.x; i < 3 * 64 * WSTRIDE / 8; i += 32) dst[i] = src[i];
    }
    __syncwarp();

    const int lane = threadIdx.x;
    const int g  = lane >> 2;
    const int tq = lane & 3;
    const int base = blockIdx.x * 16;

    int rc[2];
    #pragma unroll
    for (int i = 0; i < 2; ++i) {
        int r = base + g + 8 * i;
        rc[i] = r < B ? r : (B - 1);
    }

    // ldmatrix addressing (verified R2/R8)
    const int laneoff = (lane & 7) * WSTRIDE + (lane >> 3) * 8;
    uint32_t swb = (uint32_t)__cvta_generic_to_shared(sW);
    const uint32_t aW0 = swb + 2 * laneoff;
    const uint32_t aW1 = aW0 + 2 * (64 * WSTRIDE);
    const uint32_t aW2 = aW1 + 2 * (64 * WSTRIDE);

    // ---- hoist Wh0 B-fragments to registers: 64 words, loop-invariant ----
    uint32_t wf0[64];   // [(kp*8+nt)*4 + {x,y,z,w}]
    #pragma unroll
    for (int kp = 0; kp < 2; ++kp) {
        #pragma unroll
        for (int nt = 0; nt < 8; ++nt) {
            uint32_t off = 2 * (uint32_t)(nt * 8 * WSTRIDE + kp * 32);
            int bi = (kp * 8 + nt) * 4;
            ldsm4(wf0[bi + 0], wf0[bi + 1], wf0[bi + 2], wf0[bi + 3], aW0 + off);
        }
    }

    float b1f[16];
    #pragma unroll
    for (int nt = 0; nt < 8; ++nt) {
        b1f[nt * 2]     = b1[nt * 8 + tq * 2];
        b1f[nt * 2 + 1] = b1[nt * 8 + tq * 2 + 1];
    }

    float    accA[32], accB[32];   // [i(2)][nt(8)][e(2)]
    uint32_t h0f[16], h1f[16];     // A-frags [k(4)][q(4)]
    #pragma unroll
    for (int i = 0; i < 16; ++i) { h0f[i] = 0u; h1f[i] = 0u; }

    // step-0 gather: 16 contiguous floats per lane per row (4x float4)
    #pragma unroll
    for (int i = 0; i < 2; ++i) {
        int tok = g_tokT[rc[i]];
        const float4* rowp = reinterpret_cast<const float4*>(g_embW0 + tok * 64 + tq * 16);
        #pragma unroll
        for (int f = 0; f < 4; ++f) {
            float4 v = rowp[f];
            accA[i*16 + f*4 + 0] = v.x;
            accA[i*16 + f*4 + 1] = v.y;
            accA[i*16 + f*4 + 2] = v.z;
            accA[i*16 + f*4 + 3] = v.w;
        }
    }

    #pragma unroll 1
    for (int ts = 0; ts < SEQ; ++ts) {
        int tsn = (ts + 1 < SEQ) ? ts + 1 : SEQ - 1;
        int tkn[2];
        #pragma unroll
        for (int i = 0; i < 2; ++i) tkn[i] = g_tokT[tsn * B + rc[i]];

        // interleaved: accA += h0@Wh0 (reg B-frags) ; accB = b1 + h1@Wh1 (ldsm)
        #pragma unroll
        for (int kp = 0; kp < 2; ++kp) {
            #pragma unroll
            for (int nt = 0; nt < 8; ++nt) {
                uint32_t off = 2 * (uint32_t)(nt * 8 * WSTRIDE + kp * 32);
                int bi = (kp * 8 + nt) * 4;
                uint32_t x2, y2, z2, w2;
                ldsm4(x2, y2, z2, w2, aW2 + off);
                int k0 = 2 * kp;
                mma16816(accA[nt*2], accA[nt*2+1], accA[16+nt*2], accA[16+nt*2+1],
                         h0f[k0*4+0], h0f[k0*4+1], h0f[k0*4+2], h0f[k0*4+3],
                         wf0[bi + 0], wf0[bi + 1]);
                if (kp == 0) {
                    mma16816_c(accB[nt*2], accB[nt*2+1], accB[16+nt*2], accB[16+nt*2+1],
                               h1f[0], h1f[1], h1f[2], h1f[3], x2, y2,
                               b1f[2*nt], b1f[2*nt+1]);
                } else {
                    mma16816(accB[nt*2], accB[nt*2+1], accB[16+nt*2], accB[16+nt*2+1],
                             h1f[k0*4+0], h1f[k0*4+1], h1f[k0*4+2], h1f[k0*4+3], x2, y2);
                }
                mma16816(accA[nt*2], accA[nt*2+1], accA[16+nt*2], accA[16+nt*2+1],
                         h0f[(k0+1)*4+0], h0f[(k0+1)*4+1], h0f[(k0+1)*4+2], h0f[(k0+1)*4+3],
                         wf0[bi + 2], wf0[bi + 3]);
                mma16816(accB[nt*2], accB[nt*2+1], accB[16+nt*2], accB[16+nt*2+1],
                         h1f[(k0+1)*4+0], h1f[(k0+1)*4+1], h1f[(k0+1)*4+2], h1f[(k0+1)*4+3],
                         z2, w2);
            }
        }

        // h0 = tanh(accA) -> A-frags
        tanh_frags(accA, h0f);

        // prefetch next-step gather into accA (covers L2 latency over layer 1)
        #pragma unroll
        for (int i = 0; i < 2; ++i) {
            const float4* rowp =
                reinterpret_cast<const float4*>(g_embW0 + tkn[i] * 64 + tq * 16);
            #pragma unroll
            for (int f = 0; f < 4; ++f) {
                float4 v = rowp[f];
                accA[i*16 + f*4 + 0] = v.x;
                accA[i*16 + f*4 + 1] = v.y;
                accA[i*16 + f*4 + 2] = v.z;
                accA[i*16 + f*4 + 3] = v.w;
            }
        }

        // accB += h0new @ Wx1 (ldsm)
        #pragma unroll
        for (int kp = 0; kp < 2; ++kp) {
            #pragma unroll
            for (int nt = 0; nt < 8; ++nt) {
                uint32_t off = 2 * (uint32_t)(nt * 8 * WSTRIDE + kp * 32);
                uint32_t x1, y1, z1, w1;
                ldsm4(x1, y1, z1, w1, aW1 + off);
                int k0 = 2 * kp;
                mma16816(accB[nt*2], accB[nt*2+1], accB[16+nt*2], accB[16+nt*2+1],
                         h0f[k0*4+0], h0f[k0*4+1], h0f[k0*4+2], h0f[k0*4+3], x1, y1);
                mma16816(accB[nt*2], accB[nt*2+1], accB[16+nt*2], accB[16+nt*2+1],
                         h0f[(k0+1)*4+0], h0f[(k0+1)*4+1], h0f[(k0+1)*4+2], h0f[(k0+1)*4+3],
                         z1, w1);
            }
        }

        // h1 = tanh(accB) -> A-frags
        tanh_frags(accB, h1f);
    }

    // ---- head: sigmoid(tanh(accB) @ Wout + bout), fp32 tanh on final step ----
    float wo[16];
    #pragma unroll
    for (int nt = 0; nt < 8; ++nt) {
        float2 v = *reinterpret_cast<const float2*>(Wout + nt * 8 + tq * 2);
        wo[nt * 2] = v.x; wo[nt * 2 + 1] = v.y;
    }
    float bo = bout[0];
    #pragma unroll
    for (int i = 0; i < 2; ++i) {
        float s = 0.f;
        #pragma unroll
        for (int nt = 0; nt < 8; ++nt) {
            s += fast_tanh(accB[i * 16 + nt * 2])     * wo[nt * 2];
            s += fast_tanh(accB[i * 16 + nt * 2 + 1]) * wo[nt * 2 + 1];
        }
        s += __shfl_xor_sync(0xffffffffu, s, 1);
        s += __shfl_xor_sync(0xffffffffu, s, 2);
        int r = base + g + 8 * i;
        if (tq == 0 && r < B)
            out[r] = 1.0f / (1.0f + __expf(-(s + bo)));
    }
}

// ---------------------------------------------------------------------------
extern "C" void kernel_launch(void* const* d_in, const int* in_sizes, int n_in,
                              void* d_out, int out_size) {
    const int*   tokens = (const int*)  d_in[0];
    const float* emb    = (const float*)d_in[1];
    const float* Wx0    = (const float*)d_in[2];
    const float* Wh0    = (const float*)d_in[3];
    const float* b0     = (const float*)d_in[4];
    const float* Wx1    = (const float*)d_in[5];
    const float* Wh1    = (const float*)d_in[6];
    const float* b1     = (const float*)d_in[7];
    const float* Wout   = (const float*)d_in[8];
    const float* bout   = (const float*)d_in[9];
    float* out = (float*)d_out;

    int B = in_sizes[0] / SEQ;
    if (B > BMAX) B = BMAX;

    int prep_blocks = EMBW_BLOCKS + 1 + (B + 255) / 256;
    prep_kernel<<<prep_blocks, 256>>>(emb, Wx0, b0, Wh0, Wx1, Wh1, tokens, B);

    int nblocks = (B + 15) / 16;
    rnn_kernel<<<nblocks, 32>>>(b1, Wout, bout, out, B);
}